// round 9
// baseline (speedup 1.0000x reference)
#include <cuda_runtime.h>
#include <cuda_fp16.h>

// Problem constants (fixed by setup_inputs)
constexpr int B  = 2;
constexpr int V  = 6;
constexpr int C  = 256;
constexpr int Q  = 900;
constexpr int KP = 4;
constexpr int H0 = 56, W0 = 100;
constexpr int H1 = 28, W1 = 50;

constexpr int HW0 = H0 * W0;   // 5600
constexpr int HW1 = H1 * W1;   // 1400

constexpr int L0_ELEMS = B * V * C * HW0;   // 17,203,200
constexpr int L1_ELEMS = B * V * C * HW1;   //  4,300,800

constexpr int T0 = (HW0 + 63) / 64;   // 88 hw tiles (level 0)
constexpr int T1 = (HW1 + 63) / 64;   // 22 hw tiles (level 1)
constexpr int NTILE = T0 + T1;        // 110
constexpr int BV = B * V;             // 12
constexpr int NTOUCH = NTILE * BV;            // 1320 tile slots
constexpr int NTW    = (NTOUCH + 31) / 32;    // 42 bitmask words

// Role partition of the single grid
constexpr int NPROJ = (B * Q) / 8;                  // 225
constexpr int NTR   = NTILE * (C / 64) * BV;        // 5280
constexpr int NSAMP = B * Q;                        // 1800
constexpr int NBLK  = NPROJ + NTR + NSAMP;          // 7305

// Channel-last fp16 scratch: [B,V,H,W,C] level 0 then level 1 (~43 MB)
__device__ __half   g_feat_h[L0_ELEMS + L1_ELEMS];
// Touch bitmask (zero-initialized at load; re-cleared each call by sample bq==0)
__device__ unsigned g_touch[NTW];
// Compact tap lists per query: {w (float bits), offset}
__device__ uint2    g_taps[B * Q * 192];
__device__ int      g_ntaps[B * Q];
__device__ float    g_inv[B * Q];
// Phase counters (zero-init; reset by the last sample block each call)
__device__ volatile unsigned g_proj_done;
__device__ volatile unsigned g_tr_done;
__device__ unsigned          g_fin;

__global__ __launch_bounds__(256) void fused_k(
    const float* __restrict__ f8,     // [B,V,C,H0,W0]
    const float* __restrict__ f16,    // [B,V,C,H1,W1]
    const float* __restrict__ refs,   // [B,Q,3]
    const float* __restrict__ intr,   // [B,V,3,3]
    const float* __restrict__ extr,   // [B,V,4,4]
    const float* __restrict__ kps,    // [KP,3]
    float* __restrict__ out)          // [B,Q,C]
{
    __shared__ union {
        float tile[64][65];                   // transpose role (16.6 KB)
        struct {
            uint2 tap[192];                   // sample role staging
            float part[8][8][33];             // sample role partials
        } s;
        unsigned touch[NTW];                  // proj role bitmap
    } sm;

    const int bid = blockIdx.x;
    const int tid = threadIdx.x;

    // =====================================================================
    // Role 1: projection + tap compaction (one warp per query)
    // =====================================================================
    if (bid < NPROJ) {
        const int wid = tid >> 5;
        const int ln  = tid & 31;
        const int bq  = bid * 8 + wid;
        const int b   = bq / Q;

        if (tid < NTW) sm.touch[tid] = 0u;
        __syncthreads();

        unsigned m = 0;          // live-tap bitmask, bit = lev*4 + corner
        float tw[8];
        int   toff[8];
        bool  valid = false;

        if (ln < V * KP) {
            const int v = ln >> 2;
            const int k = ln & 3;

            const float* r  = refs + bq * 3;
            const float* kp = kps + k * 3;
            const float px = r[0] + kp[0];
            const float py = r[1] + kp[1];
            const float pz = r[2] + kp[2];

            const float* E  = extr + (b * V + v) * 16;
            const float* Km = intr + (b * V + v) * 9;

            const float cx = E[0] * px + E[1] * py + E[2]  * pz + E[3];
            const float cy = E[4] * px + E[5] * py + E[6]  * pz + E[7];
            const float cz = E[8] * px + E[9] * py + E[10] * pz + E[11];

            const float u0 = Km[0] * cx + Km[1] * cy + Km[2] * cz;
            const float u1 = Km[3] * cx + Km[4] * cy + Km[5] * cz;
            const float z  = Km[6] * cx + Km[7] * cy + Km[8] * cz;

            valid = (z > 0.0f);
            if (valid) {
                const float zs = fmaxf(z, 1e-5f);
                const float xf = u0 / zs;
                const float yf = u1 / zs;
                const int bvg  = b * V + v;

                #pragma unroll
                for (int lev = 0; lev < 2; lev++) {
                    const int H    = lev ? H1 : H0;
                    const int W    = lev ? W1 : W0;
                    const int base = (lev ? L0_ELEMS : 0) + bvg * H * W * C;

                    const float x = fminf(fmaxf(xf, -2.0f), (float)(W + 2));
                    const float y = fminf(fmaxf(yf, -2.0f), (float)(H + 2));
                    const float x0f = floorf(x), y0f = floorf(y);
                    const int x0 = (int)x0f, y0 = (int)y0f;
                    const float wx = x - x0f, wy = y - y0f;

                    int lastTile = -1;
                    #pragma unroll
                    for (int t = 0; t < 4; t++) {
                        const int xi = x0 + (t & 1);
                        const int yi = y0 + (t >> 1);
                        const bool inb = (xi >= 0) & (xi < W) & (yi >= 0) & (yi < H);
                        const float fx = (t & 1) ? wx : (1.0f - wx);
                        const float fy = (t >> 1) ? wy : (1.0f - wy);
                        const float wgt = fx * fy;
                        const int j = lev * 4 + t;
                        if (inb && wgt != 0.0f) {
                            const int hw = yi * W + xi;
                            m |= (1u << j);
                            tw[j]   = wgt;
                            toff[j] = base + hw * C;
                            const int tile = ((lev ? T0 : 0) + (hw >> 6)) * BV + bvg;
                            if (tile != lastTile) {
                                atomicOr(&sm.touch[tile >> 5], 1u << (tile & 31));
                                lastTile = tile;
                            }
                        }
                    }
                }
            }
        }

        // Warp exclusive scan (order-preserving compaction)
        const int cnt = __popc(m);
        int incl = cnt;
        #pragma unroll
        for (int d = 1; d < 32; d <<= 1) {
            const int n = __shfl_up_sync(0xffffffffu, incl, d);
            if (ln >= d) incl += n;
        }
        const int nTaps = __shfl_sync(0xffffffffu, incl, 31);
        int idx = incl - cnt;

        if (m) {
            #pragma unroll
            for (int j = 0; j < 8; j++) {
                if (m & (1u << j)) {
                    g_taps[bq * 192 + idx] =
                        make_uint2(__float_as_uint(tw[j]), (unsigned)toff[j]);
                    idx++;
                }
            }
        }

        const unsigned vb = __ballot_sync(0xffffffffu, valid);
        if (ln == 0) {
            g_ntaps[bq] = nTaps;
            g_inv[bq]   = 1.0f / (2.0f * fmaxf((float)__popc(vb), 1.0f));
        }

        __syncthreads();
        if (tid < NTW) {
            const unsigned w = sm.touch[tid];
            if (w) atomicOr(&g_touch[tid], w);
        }
        __syncthreads();
        if (tid == 0) {
            __threadfence();
            atomicAdd((unsigned*)&g_proj_done, 1u);
        }
        return;
    }

    // =====================================================================
    // Role 2: conditional transpose (waits for projection phase)
    // =====================================================================
    if (bid < NPROJ + NTR) {
        const int tb   = bid - NPROJ;
        const int bx   = tb % NTILE;
        const int rest = tb / NTILE;
        const int cy   = rest & 3;        // C/64 = 4
        const int bv   = rest >> 2;

        if (tid == 0) {
            while (g_proj_done != (unsigned)NPROJ) __nanosleep(64);
            __threadfence();
        }
        __syncthreads();

        const int ts = bx * BV + bv;
        if (((g_touch[ts >> 5] >> (ts & 31)) & 1u) == 0u) {
            if (tid == 0) atomicAdd((unsigned*)&g_tr_done, 1u);
            return;
        }

        const float* src;
        __half* dst;
        int HW, hw0;
        if (bx < T0) { src = f8;  dst = g_feat_h;            HW = HW0; hw0 = bx * 64; }
        else         { src = f16; dst = g_feat_h + L0_ELEMS; HW = HW1; hw0 = (bx - T0) * 64; }

        const int c0 = cy * 64;
        src += (size_t)bv * C * HW;
        dst += (size_t)bv * HW * C;

        #pragma unroll
        for (int i = 0; i < 4; i++) {
            const int task = tid + i * 256;
            const int slot = task & 15;
            const int cc   = task >> 4;
            const int hw   = hw0 + slot * 4;
            if (hw < HW) {
                const float4 f = *(const float4*)(src + (size_t)(c0 + cc) * HW + hw);
                sm.tile[slot * 4 + 0][cc] = f.x;
                sm.tile[slot * 4 + 1][cc] = f.y;
                sm.tile[slot * 4 + 2][cc] = f.z;
                sm.tile[slot * 4 + 3][cc] = f.w;
            }
        }
        __syncthreads();

        #pragma unroll
        for (int i = 0; i < 4; i++) {
            const int task  = tid + i * 256;
            const int cslot = task & 15;
            const int hw    = task >> 4;
            const int hwg   = hw0 + hw;
            if (hwg < HW) {
                const __half2 h01 = __floats2half2_rn(sm.tile[hw][cslot * 4 + 0],
                                                      sm.tile[hw][cslot * 4 + 1]);
                const __half2 h23 = __floats2half2_rn(sm.tile[hw][cslot * 4 + 2],
                                                      sm.tile[hw][cslot * 4 + 3]);
                uint2 u;
                u.x = *(const unsigned int*)&h01;
                u.y = *(const unsigned int*)&h23;
                *(uint2*)(dst + (size_t)hwg * C + c0 + cslot * 4) = u;
            }
        }

        __syncthreads();
        if (tid == 0) {
            __threadfence();
            atomicAdd((unsigned*)&g_tr_done, 1u);
        }
        return;
    }

    // =====================================================================
    // Role 3: gather (stages taps during transpose phase, then waits)
    // =====================================================================
    {
        const int bq = bid - NPROJ - NTR;
        const int g  = tid >> 5;   // warp 0..7
        const int ln = tid & 31;   // 8-channel slot 0..31

        // Taps depend only on projection phase — wait for it (normally already
        // satisfied by the time sample blocks are placed), then stage while
        // the transpose phase is still running.
        if (tid == 0) {
            while (g_proj_done != (unsigned)NPROJ) __nanosleep(64);
            __threadfence();
        }
        __syncthreads();

        // Re-clear touch bitmask for the next call (transpose already consumed it)
        if (bq == 0 && tid < NTW) g_touch[tid] = 0u;

        const int   nTaps = g_ntaps[bq];
        const float inv   = g_inv[bq];
        if (tid < nTaps) sm.s.tap[tid] = g_taps[bq * 192 + tid];

        if (tid == 0) {
            while (g_tr_done != (unsigned)NTR) __nanosleep(64);
            __threadfence();
        }
        __syncthreads();

        float accA[8], accB[8];
        #pragma unroll
        for (int j = 0; j < 8; j++) { accA[j] = 0.0f; accB[j] = 0.0f; }

        int t = g;
        for (; t + 8 < nTaps; t += 16) {
            const uint2 tap0 = sm.s.tap[t];
            const uint2 tap1 = sm.s.tap[t + 8];
            const float w0 = __uint_as_float(tap0.x);
            const float w1 = __uint_as_float(tap1.x);
            const uint4 q0 = ((const uint4*)(g_feat_h + (int)tap0.y))[ln];
            const uint4 q1 = ((const uint4*)(g_feat_h + (int)tap1.y))[ln];
            {
                const float2 f0 = __half22float2(*(const __half2*)&q0.x);
                const float2 f1 = __half22float2(*(const __half2*)&q0.y);
                const float2 f2 = __half22float2(*(const __half2*)&q0.z);
                const float2 f3 = __half22float2(*(const __half2*)&q0.w);
                accA[0] += w0 * f0.x;  accA[1] += w0 * f0.y;
                accA[2] += w0 * f1.x;  accA[3] += w0 * f1.y;
                accA[4] += w0 * f2.x;  accA[5] += w0 * f2.y;
                accA[6] += w0 * f3.x;  accA[7] += w0 * f3.y;
            }
            {
                const float2 f0 = __half22float2(*(const __half2*)&q1.x);
                const float2 f1 = __half22float2(*(const __half2*)&q1.y);
                const float2 f2 = __half22float2(*(const __half2*)&q1.z);
                const float2 f3 = __half22float2(*(const __half2*)&q1.w);
                accB[0] += w1 * f0.x;  accB[1] += w1 * f0.y;
                accB[2] += w1 * f1.x;  accB[3] += w1 * f1.y;
                accB[4] += w1 * f2.x;  accB[5] += w1 * f2.y;
                accB[6] += w1 * f3.x;  accB[7] += w1 * f3.y;
            }
        }
        if (t < nTaps) {
            const uint2 tap = sm.s.tap[t];
            const float wt  = __uint_as_float(tap.x);
            const uint4 qv  = ((const uint4*)(g_feat_h + (int)tap.y))[ln];
            const float2 f0 = __half22float2(*(const __half2*)&qv.x);
            const float2 f1 = __half22float2(*(const __half2*)&qv.y);
            const float2 f2 = __half22float2(*(const __half2*)&qv.z);
            const float2 f3 = __half22float2(*(const __half2*)&qv.w);
            accA[0] += wt * f0.x;  accA[1] += wt * f0.y;
            accA[2] += wt * f1.x;  accA[3] += wt * f1.y;
            accA[4] += wt * f2.x;  accA[5] += wt * f2.y;
            accA[6] += wt * f3.x;  accA[7] += wt * f3.y;
        }

        #pragma unroll
        for (int j = 0; j < 8; j++) sm.s.part[g][j][ln] = accA[j] + accB[j];
        __syncthreads();

        // Parallel reduce: thread tid owns channel tid.
        const int slot = tid >> 3;   // 0..31
        const int j    = tid & 7;    // 0..7
        float sum = 0.0f;
        #pragma unroll
        for (int w = 0; w < 8; w++) sum += sm.s.part[w][j][slot];
        out[(size_t)bq * C + tid] = sum * inv;

        // Last sample block resets the phase counters for the next call.
        __syncthreads();
        if (tid == 0) {
            const unsigned d = atomicAdd(&g_fin, 1u);
            if (d == (unsigned)(NSAMP - 1)) {
                g_proj_done = 0u;
                g_tr_done   = 0u;
                g_fin       = 0u;
            }
        }
    }
}

extern "C" void kernel_launch(void* const* d_in, const int* in_sizes, int n_in,
                              void* d_out, int out_size)
{
    const float* f8   = (const float*)d_in[0];
    const float* f16  = (const float*)d_in[1];
    const float* refs = (const float*)d_in[2];
    const float* intr = (const float*)d_in[3];
    const float* extr = (const float*)d_in[4];
    const float* kps  = (const float*)d_in[5];
    float* out = (float*)d_out;

    fused_k<<<NBLK, 256>>>(f8, f16, refs, intr, extr, kps, out);
    (void)in_sizes; (void)n_in; (void)out_size;
}

// round 10
// speedup vs baseline: 1.6496x; 1.6496x over previous
#include <cuda_runtime.h>
#include <cuda_fp16.h>

// Problem constants (fixed by setup_inputs)
constexpr int B  = 2;
constexpr int V  = 6;
constexpr int C  = 256;
constexpr int Q  = 900;
constexpr int KP = 4;
constexpr int H0 = 56, W0 = 100;
constexpr int H1 = 28, W1 = 50;

constexpr int HW0 = H0 * W0;   // 5600
constexpr int HW1 = H1 * W1;   // 1400

constexpr int L0_ELEMS = B * V * C * HW0;   // 17,203,200
constexpr int L1_ELEMS = B * V * C * HW1;   //  4,300,800

constexpr int T0 = (HW0 + 63) / 64;   // 88 hw tiles (level 0)
constexpr int T1 = (HW1 + 63) / 64;   // 22 hw tiles (level 1)
constexpr int NTILE = T0 + T1;        // 110
constexpr int BV = B * V;             // 12
constexpr int NTOUCH = NTILE * BV;            // 1320 tile slots
constexpr int NTW    = (NTOUCH + 31) / 32;    // 42 bitmask words

// Channel-last fp16 scratch: [B,V,H,W,C] level 0 then level 1 (~43 MB)
__device__ __half   g_feat_h[L0_ELEMS + L1_ELEMS];
// Touch bitmask (zero-initialized at load; re-cleared by sample_k each call)
__device__ unsigned g_touch[NTW];
// Compact tap lists per query (+256 pad: speculative staging overreads)
__device__ uint2    g_taps[B * Q * 192 + 256];
__device__ int      g_ntaps[B * Q];
__device__ float    g_inv[B * Q];

// ---------------------------------------------------------------------------
// Projection + compaction: one WARP per query, lane = sample (24 active).
// Touch tiles aggregated in a per-block smem bitmap, flushed with atomicOr.
// ---------------------------------------------------------------------------
__global__ __launch_bounds__(256) void proj_k(
    const float* __restrict__ refs,   // [B,Q,3]
    const float* __restrict__ intr,   // [B,V,3,3]
    const float* __restrict__ extr,   // [B,V,4,4]
    const float* __restrict__ kps)    // [KP,3]
{
    __shared__ unsigned s_touch[NTW];

    const int tid = threadIdx.x;
    const int wid = tid >> 5;
    const int ln  = tid & 31;
    const int bq  = blockIdx.x * 8 + wid;   // 225 blocks x 8 warps = 1800
    const int b   = bq / Q;

    if (tid < NTW) s_touch[tid] = 0u;
    __syncthreads();

    unsigned m = 0;          // live-tap bitmask, bit = lev*4 + corner
    float tw[8];
    int   toff[8];
    bool  valid = false;

    if (ln < V * KP) {
        const int v = ln >> 2;
        const int k = ln & 3;

        const float* r  = refs + bq * 3;
        const float* kp = kps + k * 3;
        const float px = r[0] + kp[0];
        const float py = r[1] + kp[1];
        const float pz = r[2] + kp[2];

        const float* E  = extr + (b * V + v) * 16;
        const float* Km = intr + (b * V + v) * 9;

        const float cx = E[0] * px + E[1] * py + E[2]  * pz + E[3];
        const float cy = E[4] * px + E[5] * py + E[6]  * pz + E[7];
        const float cz = E[8] * px + E[9] * py + E[10] * pz + E[11];

        const float u0 = Km[0] * cx + Km[1] * cy + Km[2] * cz;
        const float u1 = Km[3] * cx + Km[4] * cy + Km[5] * cz;
        const float z  = Km[6] * cx + Km[7] * cy + Km[8] * cz;

        valid = (z > 0.0f);
        if (valid) {
            const float zs = fmaxf(z, 1e-5f);
            const float xf = u0 / zs;
            const float yf = u1 / zs;
            const int bvg  = b * V + v;

            #pragma unroll
            for (int lev = 0; lev < 2; lev++) {
                const int H    = lev ? H1 : H0;
                const int W    = lev ? W1 : W0;
                const int base = (lev ? L0_ELEMS : 0) + bvg * H * W * C;

                const float x = fminf(fmaxf(xf, -2.0f), (float)(W + 2));
                const float y = fminf(fmaxf(yf, -2.0f), (float)(H + 2));
                const float x0f = floorf(x), y0f = floorf(y);
                const int x0 = (int)x0f, y0 = (int)y0f;
                const float wx = x - x0f, wy = y - y0f;

                int lastTile = -1;
                #pragma unroll
                for (int t = 0; t < 4; t++) {
                    const int xi = x0 + (t & 1);
                    const int yi = y0 + (t >> 1);
                    const bool inb = (xi >= 0) & (xi < W) & (yi >= 0) & (yi < H);
                    const float fx = (t & 1) ? wx : (1.0f - wx);
                    const float fy = (t >> 1) ? wy : (1.0f - wy);
                    const float wgt = fx * fy;
                    const int j = lev * 4 + t;
                    if (inb && wgt != 0.0f) {
                        const int hw = yi * W + xi;
                        m |= (1u << j);
                        tw[j]   = wgt;
                        toff[j] = base + hw * C;
                        const int tile = ((lev ? T0 : 0) + (hw >> 6)) * BV + bvg;
                        if (tile != lastTile) {
                            atomicOr(&s_touch[tile >> 5], 1u << (tile & 31));
                            lastTile = tile;
                        }
                    }
                }
            }
        }
    }

    // Warp exclusive scan of per-lane live counts (order-preserving)
    const int cnt = __popc(m);
    int incl = cnt;
    #pragma unroll
    for (int d = 1; d < 32; d <<= 1) {
        const int n = __shfl_up_sync(0xffffffffu, incl, d);
        if (ln >= d) incl += n;
    }
    const int nTaps = __shfl_sync(0xffffffffu, incl, 31);
    int idx = incl - cnt;

    if (m) {
        #pragma unroll
        for (int j = 0; j < 8; j++) {
            if (m & (1u << j)) {
                g_taps[bq * 192 + idx] =
                    make_uint2(__float_as_uint(tw[j]), (unsigned)toff[j]);
                idx++;
            }
        }
    }

    const unsigned vb = __ballot_sync(0xffffffffu, valid);
    if (ln == 0) {
        g_ntaps[bq] = nTaps;
        g_inv[bq]   = 1.0f / (2.0f * fmaxf((float)__popc(vb), 1.0f));
    }

    __syncthreads();
    if (tid < NTW) {
        const unsigned w = s_touch[tid];
        if (w) atomicOr(&g_touch[tid], w);   // RED (return unused)
    }
}

// ---------------------------------------------------------------------------
// Conditional transpose [BV, C, HW] (fp32) -> [BV, HW, C] (fp16).
// Tile = 64 hw x 64 c, 256 threads, 4 independent float4 LDGs / 4 uint2 STGs
// per thread. Untouched tiles exit immediately.
// ---------------------------------------------------------------------------
__global__ __launch_bounds__(256) void transpose_fused_k(
    const float* __restrict__ f8, const float* __restrict__ f16)
{
    __shared__ float tile[64][65];   // [hw_local][c_local]

    const int bx = blockIdx.x;
    const int bv = blockIdx.z;
    const int tslot = bx * BV + bv;
    if ((g_touch[tslot >> 5] & (1u << (tslot & 31))) == 0u) return;

    const float* src;
    __half* dst;
    int HW, hw0;
    if (bx < T0) { src = f8;  dst = g_feat_h;            HW = HW0; hw0 = bx * 64; }
    else         { src = f16; dst = g_feat_h + L0_ELEMS; HW = HW1; hw0 = (bx - T0) * 64; }

    const int c0 = blockIdx.y * 64;
    src += (size_t)bv * C * HW;
    dst += (size_t)bv * HW * C;
    const int tid = threadIdx.x;

    // Load phase: 1024 float4 tasks (16 hw-slots x 64 channels), 4 per thread.
    #pragma unroll
    for (int i = 0; i < 4; i++) {
        const int task = tid + i * 256;
        const int slot = task & 15;       // hw float4 slot (0..15)
        const int cc   = task >> 4;       // channel within tile (0..63)
        const int hw   = hw0 + slot * 4;
        if (hw < HW) {                    // HW % 4 == 0, float4-safe
            const float4 f = *(const float4*)(src + (size_t)(c0 + cc) * HW + hw);
            tile[slot * 4 + 0][cc] = f.x;
            tile[slot * 4 + 1][cc] = f.y;
            tile[slot * 4 + 2][cc] = f.z;
            tile[slot * 4 + 3][cc] = f.w;
        }
    }
    __syncthreads();

    // Store phase: 1024 half4 tasks (64 hw x 16 c-slots), 4 per thread.
    #pragma unroll
    for (int i = 0; i < 4; i++) {
        const int task  = tid + i * 256;
        const int cslot = task & 15;      // c half4 slot (0..15)
        const int hw    = task >> 4;      // hw within tile (0..63)
        const int hwg   = hw0 + hw;
        if (hwg < HW) {
            const __half2 h01 = __floats2half2_rn(tile[hw][cslot * 4 + 0],
                                                  tile[hw][cslot * 4 + 1]);
            const __half2 h23 = __floats2half2_rn(tile[hw][cslot * 4 + 2],
                                                  tile[hw][cslot * 4 + 3]);
            uint2 u;
            u.x = *(const unsigned int*)&h01;
            u.y = *(const unsigned int*)&h23;
            *(uint2*)(dst + (size_t)hwg * C + c0 + cslot * 4) = u;
        }
    }
}

// ---------------------------------------------------------------------------
// Gather kernel: TWO queries per block (grid 900 = one full wave), 4 warps
// per query. Taps register-staged per warp (speculative, shfl-broadcast) —
// no staging smem, no staging barrier. Parallel reduce, coalesced stores.
// Block 0 re-clears the touch bitmask for the next call.
// ---------------------------------------------------------------------------
__global__ __launch_bounds__(256) void sample_k(float* __restrict__ out)
{
    __shared__ float s_part[8][8][33];   // [warp][chan-in-slot][slot] (padded)

    const int tid = threadIdx.x;
    const int g   = tid >> 5;    // warp 0..7
    const int ln  = tid & 31;    // lane: 8-channel slot 0..31
    const int qh  = g >> 2;      // 0 = query A, 1 = query B
    const int g4  = g & 3;       // warp-within-query 0..3

    const int bqA = blockIdx.x * 2;
    const int bq  = bqA + qh;

    // Re-clear touch bitmask for the next call (transpose already consumed it)
    if (blockIdx.x == 0 && tid < NTW) g_touch[tid] = 0u;

    // Speculative register staging: lane ln holds taps (g4 + 4*ln) and
    // (g4 + 4*(ln+32)). Covers tap indices 0..255 >= 192 max. Padded array.
    const int tbase = bq * 192 + g4;
    const uint2 t0 = g_taps[tbase + 4 * ln];
    const uint2 t1 = g_taps[tbase + 4 * (ln + 32)];
    const int nTaps = g_ntaps[bq];

    float accA[8], accB[8];
    #pragma unroll
    for (int j = 0; j < 8; j++) { accA[j] = 0.0f; accB[j] = 0.0f; }

    const int nIter = (nTaps - g4 + 3) >> 2;   // taps owned by this warp

    int i = 0;
    for (; i + 1 < nIter; i += 2) {
        const unsigned w0u = __shfl_sync(0xffffffffu, i < 32 ? t0.x : t1.x, i & 31);
        const unsigned o0u = __shfl_sync(0xffffffffu, i < 32 ? t0.y : t1.y, i & 31);
        const int i1 = i + 1;
        const unsigned w1u = __shfl_sync(0xffffffffu, i1 < 32 ? t0.x : t1.x, i1 & 31);
        const unsigned o1u = __shfl_sync(0xffffffffu, i1 < 32 ? t0.y : t1.y, i1 & 31);
        const float w0 = __uint_as_float(w0u);
        const float w1 = __uint_as_float(w1u);
        const uint4 q0 = ((const uint4*)(g_feat_h + (int)o0u))[ln];
        const uint4 q1 = ((const uint4*)(g_feat_h + (int)o1u))[ln];
        {
            const float2 f0 = __half22float2(*(const __half2*)&q0.x);
            const float2 f1 = __half22float2(*(const __half2*)&q0.y);
            const float2 f2 = __half22float2(*(const __half2*)&q0.z);
            const float2 f3 = __half22float2(*(const __half2*)&q0.w);
            accA[0] += w0 * f0.x;  accA[1] += w0 * f0.y;
            accA[2] += w0 * f1.x;  accA[3] += w0 * f1.y;
            accA[4] += w0 * f2.x;  accA[5] += w0 * f2.y;
            accA[6] += w0 * f3.x;  accA[7] += w0 * f3.y;
        }
        {
            const float2 f0 = __half22float2(*(const __half2*)&q1.x);
            const float2 f1 = __half22float2(*(const __half2*)&q1.y);
            const float2 f2 = __half22float2(*(const __half2*)&q1.z);
            const float2 f3 = __half22float2(*(const __half2*)&q1.w);
            accB[0] += w1 * f0.x;  accB[1] += w1 * f0.y;
            accB[2] += w1 * f1.x;  accB[3] += w1 * f1.y;
            accB[4] += w1 * f2.x;  accB[5] += w1 * f2.y;
            accB[6] += w1 * f3.x;  accB[7] += w1 * f3.y;
        }
    }
    if (i < nIter) {
        const unsigned wu = __shfl_sync(0xffffffffu, i < 32 ? t0.x : t1.x, i & 31);
        const unsigned ou = __shfl_sync(0xffffffffu, i < 32 ? t0.y : t1.y, i & 31);
        const float wt = __uint_as_float(wu);
        const uint4 qv = ((const uint4*)(g_feat_h + (int)ou))[ln];
        const float2 f0 = __half22float2(*(const __half2*)&qv.x);
        const float2 f1 = __half22float2(*(const __half2*)&qv.y);
        const float2 f2 = __half22float2(*(const __half2*)&qv.z);
        const float2 f3 = __half22float2(*(const __half2*)&qv.w);
        accA[0] += wt * f0.x;  accA[1] += wt * f0.y;
        accA[2] += wt * f1.x;  accA[3] += wt * f1.y;
        accA[4] += wt * f2.x;  accA[5] += wt * f2.y;
        accA[6] += wt * f3.x;  accA[7] += wt * f3.y;
    }

    #pragma unroll
    for (int j = 0; j < 8; j++) s_part[g][j][ln] = accA[j] + accB[j];
    __syncthreads();

    // Parallel reduce: thread tid owns channel tid for BOTH queries.
    const int slot = tid >> 3;   // 0..31
    const int j    = tid & 7;    // 0..7
    float sumA = 0.0f, sumB = 0.0f;
    #pragma unroll
    for (int w = 0; w < 4; w++) {
        sumA += s_part[w][j][slot];
        sumB += s_part[w + 4][j][slot];
    }
    out[(size_t)bqA * C + tid]       = sumA * g_inv[bqA];
    out[(size_t)(bqA + 1) * C + tid] = sumB * g_inv[bqA + 1];
}

extern "C" void kernel_launch(void* const* d_in, const int* in_sizes, int n_in,
                              void* d_out, int out_size)
{
    const float* f8   = (const float*)d_in[0];
    const float* f16  = (const float*)d_in[1];
    const float* refs = (const float*)d_in[2];
    const float* intr = (const float*)d_in[3];
    const float* extr = (const float*)d_in[4];
    const float* kps  = (const float*)d_in[5];
    float* out = (float*)d_out;

    proj_k<<<(B * Q) / 8, 256>>>(refs, intr, extr, kps);
    transpose_fused_k<<<dim3(NTILE, C / 64, BV), 256>>>(f8, f16);
    sample_k<<<Q, 256>>>(out);   // B*Q/2 = 900 blocks, 2 queries each
    (void)in_sizes; (void)n_in; (void)out_size;
}

// round 11
// speedup vs baseline: 1.6724x; 1.0139x over previous
#include <cuda_runtime.h>
#include <cuda_fp16.h>

// Problem constants (fixed by setup_inputs)
constexpr int B  = 2;
constexpr int V  = 6;
constexpr int C  = 256;
constexpr int Q  = 900;
constexpr int KP = 4;
constexpr int H0 = 56, W0 = 100;
constexpr int H1 = 28, W1 = 50;

constexpr int HW0 = H0 * W0;   // 5600
constexpr int HW1 = H1 * W1;   // 1400

constexpr int L0_ELEMS = B * V * C * HW0;   // 17,203,200
constexpr int L1_ELEMS = B * V * C * HW1;   //  4,300,800

constexpr int T0 = (HW0 + 63) / 64;   // 88 hw tiles (level 0)
constexpr int T1 = (HW1 + 63) / 64;   // 22 hw tiles (level 1)
constexpr int NTILE = T0 + T1;        // 110
constexpr int BV = B * V;             // 12
constexpr int NTOUCH = NTILE * BV;            // 1320 tile slots
constexpr int NTW    = (NTOUCH + 31) / 32;    // 42 bitmask words

// Channel-last fp16 scratch: [B,V,H,W,C] level 0 then level 1 (~43 MB)
__device__ __half   g_feat_h[L0_ELEMS + L1_ELEMS];
// Touch bitmask (zero-initialized at load; re-cleared by sample_k each call)
__device__ unsigned g_touch[NTW];
// Compact tap lists per query (+256 pad: speculative staging overreads)
__device__ uint2    g_taps[B * Q * 192 + 256];
__device__ int      g_ntaps[B * Q];
__device__ float    g_inv[B * Q];

// PDL intrinsics
__device__ __forceinline__ void gdc_wait()   { asm volatile("griddepcontrol.wait;" ::: "memory"); }
__device__ __forceinline__ void gdc_launch() { asm volatile("griddepcontrol.launch_dependents;" ::: "memory"); }

// ---------------------------------------------------------------------------
// Projection + compaction: one WARP per query, lane = sample (24 active).
// All E/K/kp matrices (300 floats total) staged in smem by one coalesced
// cooperative load; per-lane global traffic = 3 refs floats.
// ---------------------------------------------------------------------------
__global__ __launch_bounds__(256) void proj_k(
    const float* __restrict__ refs,   // [B,Q,3]
    const float* __restrict__ intr,   // [B,V,3,3]
    const float* __restrict__ extr,   // [B,V,4,4]
    const float* __restrict__ kps)    // [KP,3]
{
    __shared__ unsigned s_touch[NTW];
    __shared__ float sE[BV * 16];    // 192
    __shared__ float sK[BV * 9];     // 108
    __shared__ float skp[KP * 3];    // 12

    const int tid = threadIdx.x;
    const int wid = tid >> 5;
    const int ln  = tid & 31;
    const int bq  = blockIdx.x * 8 + wid;   // 225 blocks x 8 warps = 1800
    const int b   = bq / Q;

    if (tid < NTW) s_touch[tid] = 0u;
    #pragma unroll
    for (int i = tid; i < 300; i += 256) {
        if (i < 192) sE[i] = extr[i];
        else         sK[i - 192] = intr[i - 192];
    }
    if (tid < KP * 3) skp[tid] = kps[tid];
    __syncthreads();

    unsigned m = 0;          // live-tap bitmask, bit = lev*4 + corner
    float tw[8];
    int   toff[8];
    bool  valid = false;

    if (ln < V * KP) {
        const int v = ln >> 2;
        const int k = ln & 3;
        const int bvg = b * V + v;

        const float* r  = refs + bq * 3;
        const float* kp = skp + k * 3;
        const float px = r[0] + kp[0];
        const float py = r[1] + kp[1];
        const float pz = r[2] + kp[2];

        const float* E  = sE + bvg * 16;
        const float* Km = sK + bvg * 9;

        const float cx = E[0] * px + E[1] * py + E[2]  * pz + E[3];
        const float cy = E[4] * px + E[5] * py + E[6]  * pz + E[7];
        const float cz = E[8] * px + E[9] * py + E[10] * pz + E[11];

        const float u0 = Km[0] * cx + Km[1] * cy + Km[2] * cz;
        const float u1 = Km[3] * cx + Km[4] * cy + Km[5] * cz;
        const float z  = Km[6] * cx + Km[7] * cy + Km[8] * cz;

        valid = (z > 0.0f);
        if (valid) {
            const float zs = fmaxf(z, 1e-5f);
            const float xf = u0 / zs;
            const float yf = u1 / zs;

            #pragma unroll
            for (int lev = 0; lev < 2; lev++) {
                const int H    = lev ? H1 : H0;
                const int W    = lev ? W1 : W0;
                const int base = (lev ? L0_ELEMS : 0) + bvg * H * W * C;

                const float x = fminf(fmaxf(xf, -2.0f), (float)(W + 2));
                const float y = fminf(fmaxf(yf, -2.0f), (float)(H + 2));
                const float x0f = floorf(x), y0f = floorf(y);
                const int x0 = (int)x0f, y0 = (int)y0f;
                const float wx = x - x0f, wy = y - y0f;

                int lastTile = -1;
                #pragma unroll
                for (int t = 0; t < 4; t++) {
                    const int xi = x0 + (t & 1);
                    const int yi = y0 + (t >> 1);
                    const bool inb = (xi >= 0) & (xi < W) & (yi >= 0) & (yi < H);
                    const float fx = (t & 1) ? wx : (1.0f - wx);
                    const float fy = (t >> 1) ? wy : (1.0f - wy);
                    const float wgt = fx * fy;
                    const int j = lev * 4 + t;
                    if (inb && wgt != 0.0f) {
                        const int hw = yi * W + xi;
                        m |= (1u << j);
                        tw[j]   = wgt;
                        toff[j] = base + hw * C;
                        const int tile = ((lev ? T0 : 0) + (hw >> 6)) * BV + bvg;
                        if (tile != lastTile) {
                            atomicOr(&s_touch[tile >> 5], 1u << (tile & 31));
                            lastTile = tile;
                        }
                    }
                }
            }
        }
    }

    // Warp exclusive scan of per-lane live counts (order-preserving)
    const int cnt = __popc(m);
    int incl = cnt;
    #pragma unroll
    for (int d = 1; d < 32; d <<= 1) {
        const int n = __shfl_up_sync(0xffffffffu, incl, d);
        if (ln >= d) incl += n;
    }
    const int nTaps = __shfl_sync(0xffffffffu, incl, 31);
    int idx = incl - cnt;

    if (m) {
        #pragma unroll
        for (int j = 0; j < 8; j++) {
            if (m & (1u << j)) {
                g_taps[bq * 192 + idx] =
                    make_uint2(__float_as_uint(tw[j]), (unsigned)toff[j]);
                idx++;
            }
        }
    }

    const unsigned vb = __ballot_sync(0xffffffffu, valid);
    if (ln == 0) {
        g_ntaps[bq] = nTaps;
        g_inv[bq]   = 1.0f / (2.0f * fmaxf((float)__popc(vb), 1.0f));
    }

    __syncthreads();
    if (tid < NTW) {
        const unsigned w = s_touch[tid];
        if (w) atomicOr(&g_touch[tid], w);   // RED (return unused)
    }
}

// ---------------------------------------------------------------------------
// Conditional transpose [BV, C, HW] (fp32) -> [BV, HW, C] (fp16).
// PDL: waits for proj, then immediately releases sample_k's launch so its
// tap staging overlaps the transpose body.
// ---------------------------------------------------------------------------
__global__ __launch_bounds__(256) void transpose_fused_k(
    const float* __restrict__ f8, const float* __restrict__ f16)
{
    __shared__ float tile[64][65];   // [hw_local][c_local]

    gdc_wait();      // proj_k complete (g_touch, g_taps final)
    gdc_launch();    // allow sample_k to launch and stage taps

    const int bx = blockIdx.x;
    const int bv = blockIdx.z;
    const int tslot = bx * BV + bv;
    if ((g_touch[tslot >> 5] & (1u << (tslot & 31))) == 0u) return;

    const float* src;
    __half* dst;
    int HW, hw0;
    if (bx < T0) { src = f8;  dst = g_feat_h;            HW = HW0; hw0 = bx * 64; }
    else         { src = f16; dst = g_feat_h + L0_ELEMS; HW = HW1; hw0 = (bx - T0) * 64; }

    const int c0 = blockIdx.y * 64;
    src += (size_t)bv * C * HW;
    dst += (size_t)bv * HW * C;
    const int tid = threadIdx.x;

    // Load phase: 1024 float4 tasks (16 hw-slots x 64 channels), 4 per thread.
    #pragma unroll
    for (int i = 0; i < 4; i++) {
        const int task = tid + i * 256;
        const int slot = task & 15;       // hw float4 slot (0..15)
        const int cc   = task >> 4;       // channel within tile (0..63)
        const int hw   = hw0 + slot * 4;
        if (hw < HW) {                    // HW % 4 == 0, float4-safe
            const float4 f = *(const float4*)(src + (size_t)(c0 + cc) * HW + hw);
            tile[slot * 4 + 0][cc] = f.x;
            tile[slot * 4 + 1][cc] = f.y;
            tile[slot * 4 + 2][cc] = f.z;
            tile[slot * 4 + 3][cc] = f.w;
        }
    }
    __syncthreads();

    // Store phase: 1024 half4 tasks (64 hw x 16 c-slots), 4 per thread.
    #pragma unroll
    for (int i = 0; i < 4; i++) {
        const int task  = tid + i * 256;
        const int cslot = task & 15;      // c half4 slot (0..15)
        const int hw    = task >> 4;      // hw within tile (0..63)
        const int hwg   = hw0 + hw;
        if (hwg < HW) {
            const __half2 h01 = __floats2half2_rn(tile[hw][cslot * 4 + 0],
                                                  tile[hw][cslot * 4 + 1]);
            const __half2 h23 = __floats2half2_rn(tile[hw][cslot * 4 + 2],
                                                  tile[hw][cslot * 4 + 3]);
            uint2 u;
            u.x = *(const unsigned int*)&h01;
            u.y = *(const unsigned int*)&h23;
            *(uint2*)(dst + (size_t)hwg * C + c0 + cslot * 4) = u;
        }
    }
}

// ---------------------------------------------------------------------------
// Gather kernel: TWO queries per block (grid 900 = one full wave), 4 warps
// per query. PDL: launches during the transpose, stages taps (proj output —
// complete before transpose started), THEN waits for transpose completion.
// ---------------------------------------------------------------------------
__global__ __launch_bounds__(256) void sample_k(float* __restrict__ out)
{
    __shared__ float s_part[8][8][33];   // [warp][chan-in-slot][slot] (padded)

    const int tid = threadIdx.x;
    const int g   = tid >> 5;    // warp 0..7
    const int ln  = tid & 31;    // lane: 8-channel slot 0..31
    const int qh  = g >> 2;      // 0 = query A, 1 = query B
    const int g4  = g & 3;       // warp-within-query 0..3

    const int bqA = blockIdx.x * 2;
    const int bq  = bqA + qh;

    // Stage taps while the transpose phase is still running (proj output only).
    const int tbase = bq * 192 + g4;
    const uint2 t0 = g_taps[tbase + 4 * ln];
    const uint2 t1 = g_taps[tbase + 4 * (ln + 32)];
    const int   nTaps = g_ntaps[bq];
    const float invQ  = g_inv[bq];

    gdc_wait();   // transpose complete: g_feat_h valid, g_touch consumed

    // Re-clear touch bitmask for the next call
    if (blockIdx.x == 0 && tid < NTW) g_touch[tid] = 0u;

    float accA[8], accB[8];
    #pragma unroll
    for (int j = 0; j < 8; j++) { accA[j] = 0.0f; accB[j] = 0.0f; }

    const int nIter = (nTaps - g4 + 3) >> 2;   // taps owned by this warp

    int i = 0;
    for (; i + 1 < nIter; i += 2) {
        const unsigned w0u = __shfl_sync(0xffffffffu, i < 32 ? t0.x : t1.x, i & 31);
        const unsigned o0u = __shfl_sync(0xffffffffu, i < 32 ? t0.y : t1.y, i & 31);
        const int i1 = i + 1;
        const unsigned w1u = __shfl_sync(0xffffffffu, i1 < 32 ? t0.x : t1.x, i1 & 31);
        const unsigned o1u = __shfl_sync(0xffffffffu, i1 < 32 ? t0.y : t1.y, i1 & 31);
        const float w0 = __uint_as_float(w0u);
        const float w1 = __uint_as_float(w1u);
        const uint4 q0 = ((const uint4*)(g_feat_h + (int)o0u))[ln];
        const uint4 q1 = ((const uint4*)(g_feat_h + (int)o1u))[ln];
        {
            const float2 f0 = __half22float2(*(const __half2*)&q0.x);
            const float2 f1 = __half22float2(*(const __half2*)&q0.y);
            const float2 f2 = __half22float2(*(const __half2*)&q0.z);
            const float2 f3 = __half22float2(*(const __half2*)&q0.w);
            accA[0] += w0 * f0.x;  accA[1] += w0 * f0.y;
            accA[2] += w0 * f1.x;  accA[3] += w0 * f1.y;
            accA[4] += w0 * f2.x;  accA[5] += w0 * f2.y;
            accA[6] += w0 * f3.x;  accA[7] += w0 * f3.y;
        }
        {
            const float2 f0 = __half22float2(*(const __half2*)&q1.x);
            const float2 f1 = __half22float2(*(const __half2*)&q1.y);
            const float2 f2 = __half22float2(*(const __half2*)&q1.z);
            const float2 f3 = __half22float2(*(const __half2*)&q1.w);
            accB[0] += w1 * f0.x;  accB[1] += w1 * f0.y;
            accB[2] += w1 * f1.x;  accB[3] += w1 * f1.y;
            accB[4] += w1 * f2.x;  accB[5] += w1 * f2.y;
            accB[6] += w1 * f3.x;  accB[7] += w1 * f3.y;
        }
    }
    if (i < nIter) {
        const unsigned wu = __shfl_sync(0xffffffffu, i < 32 ? t0.x : t1.x, i & 31);
        const unsigned ou = __shfl_sync(0xffffffffu, i < 32 ? t0.y : t1.y, i & 31);
        const float wt = __uint_as_float(wu);
        const uint4 qv = ((const uint4*)(g_feat_h + (int)ou))[ln];
        const float2 f0 = __half22float2(*(const __half2*)&qv.x);
        const float2 f1 = __half22float2(*(const __half2*)&qv.y);
        const float2 f2 = __half22float2(*(const __half2*)&qv.z);
        const float2 f3 = __half22float2(*(const __half2*)&qv.w);
        accA[0] += wt * f0.x;  accA[1] += wt * f0.y;
        accA[2] += wt * f1.x;  accA[3] += wt * f1.y;
        accA[4] += wt * f2.x;  accA[5] += wt * f2.y;
        accA[6] += wt * f3.x;  accA[7] += wt * f3.y;
    }

    #pragma unroll
    for (int j = 0; j < 8; j++) s_part[g][j][ln] = accA[j] + accB[j];
    __syncthreads();

    // Parallel reduce: thread tid owns channel tid for BOTH queries.
    const int slot = tid >> 3;   // 0..31
    const int j    = tid & 7;    // 0..7
    float sumA = 0.0f, sumB = 0.0f;
    #pragma unroll
    for (int w = 0; w < 4; w++) {
        sumA += s_part[w][j][slot];
        sumB += s_part[w + 4][j][slot];
    }
    out[(size_t)bqA * C + tid]       = sumA * invQ * 0.0f + sumA * g_inv[bqA];
    out[(size_t)(bqA + 1) * C + tid] = sumB * g_inv[bqA + 1];
}

extern "C" void kernel_launch(void* const* d_in, const int* in_sizes, int n_in,
                              void* d_out, int out_size)
{
    const float* f8   = (const float*)d_in[0];
    const float* f16  = (const float*)d_in[1];
    const float* refs = (const float*)d_in[2];
    const float* intr = (const float*)d_in[3];
    const float* extr = (const float*)d_in[4];
    const float* kps  = (const float*)d_in[5];
    float* out = (float*)d_out;

    proj_k<<<(B * Q) / 8, 256>>>(refs, intr, extr, kps);

    cudaLaunchAttribute attrs[1];
    attrs[0].id = cudaLaunchAttributeProgrammaticStreamSerialization;
    attrs[0].val.programmaticStreamSerializationAllowed = 1;

    {
        cudaLaunchConfig_t cfg = {};
        cfg.gridDim  = dim3(NTILE, C / 64, BV);
        cfg.blockDim = dim3(256, 1, 1);
        cfg.attrs    = attrs;
        cfg.numAttrs = 1;
        cudaLaunchKernelEx(&cfg, transpose_fused_k, f8, f16);
    }
    {
        cudaLaunchConfig_t cfg = {};
        cfg.gridDim  = dim3(Q, 1, 1);      // 900 blocks, 2 queries each
        cfg.blockDim = dim3(256, 1, 1);
        cfg.attrs    = attrs;
        cfg.numAttrs = 1;
        cudaLaunchKernelEx(&cfg, sample_k, out);
    }
    (void)in_sizes; (void)n_in; (void)out_size;
}